// round 2
// baseline (speedup 1.0000x reference)
#include <cuda_runtime.h>

// x: [B=16384, F=32, E=64] fp32, contiguous. out: [B, P=496] fp32.
// s[b,f] = sum_e x[b,f,e];  out[b,p] = s[b,row(p)] * s[b,col(p)]
//
// One CTA (256 threads) per batch row.
//  - Row = 2048 floats = 512 float4. Thread t loads float4[t] and float4[t+256].
//  - float4 index i belongs to field i/16. So in warp w: lanes 0-15 hold field 2w,
//    lanes 16-31 hold field 2w+1 (first load); second load gives fields 2w+16, 2w+17.
//  - Butterfly shfl_xor over offsets 8,4,2,1 reduces within each 16-lane half.
//  - Field sums land in smem[32]; 496 outputs written coalesced (p = t, t+256).

static constexpr int BATCH = 16384;
static constexpr int NUM_PAIRS = 496;

__device__ __forceinline__ void pair_from_idx(int p, int& r, int& c) {
    // pairs (i,j), i<j, enumerated row-major: row i contributes (31 - i) pairs
    int i = 0, rem = p;
    while (rem >= 31 - i) { rem -= 31 - i; ++i; }
    r = i;
    c = i + 1 + rem;
}

__global__ __launch_bounds__(256) void opn_kernel(const float4* __restrict__ x,
                                                  float* __restrict__ out) {
    const int b = blockIdx.x;
    const float4* row = x + (size_t)b * 512;   // 512 float4 per batch row
    const int tid = threadIdx.x;

    float4 v0 = row[tid];
    float4 v1 = row[tid + 256];
    float s0 = (v0.x + v0.y) + (v0.z + v0.w);
    float s1 = (v1.x + v1.y) + (v1.z + v1.w);

    // reduce within each 16-lane half of the warp
    #pragma unroll
    for (int o = 8; o >= 1; o >>= 1) {
        s0 += __shfl_xor_sync(0xffffffffu, s0, o);
        s1 += __shfl_xor_sync(0xffffffffu, s1, o);
    }

    __shared__ float s[32];
    const int lane = tid & 31;
    const int w = tid >> 5;
    if (lane == 0)  { s[2 * w]          = s0; s[2 * w + 16]     = s1; }
    if (lane == 16) { s[2 * w + 1]      = s0; s[2 * w + 17]     = s1; }
    __syncthreads();

    float* o = out + (size_t)b * NUM_PAIRS;
    #pragma unroll
    for (int p = tid; p < NUM_PAIRS; p += 256) {
        int r, c;
        pair_from_idx(p, r, c);
        o[p] = s[r] * s[c];
    }
}

extern "C" void kernel_launch(void* const* d_in, const int* in_sizes, int n_in,
                              void* d_out, int out_size) {
    const float4* x = (const float4*)d_in[0];
    float* out = (float*)d_out;
    opn_kernel<<<BATCH, 256>>>(x, out);
}

// round 3
// speedup vs baseline: 1.0599x; 1.0599x over previous
#include <cuda_runtime.h>

// x: [B=16384, F=32, E=64] fp32 contiguous. out: [B, P=496] fp32.
// s[b,f] = sum_e x[b,f,e];  out[b,p] = s[b,row(p)] * s[b,col(p)]
//
// One CTA (256 threads) per batch row:
//  - thread t loads float4 row[2t], row[2t+1]  (16 consecutive floats, all in
//    field t>>3, since a field = 64 floats = 16 float4 = 8 threads).
//  - local sum of 8 floats, then 3-step butterfly over 8 lanes -> field sum.
//  - field sums to smem fs[32] (one word per bank, reads broadcast).
//  - threads 0..123 each produce 4 products via closed-form pair index
//    (no loop) and store one float4 (out rows are 16B aligned: 496*4=1984B).

static constexpr int BATCH = 16384;

__global__ __launch_bounds__(256) void opn_kernel(const float4* __restrict__ x,
                                                  float* __restrict__ out) {
    const int b = blockIdx.x;
    const float4* row = x + (size_t)b * 512;   // 512 float4 per batch row
    const int t = threadIdx.x;

    float4 v0 = row[2 * t];
    float4 v1 = row[2 * t + 1];
    float s = ((v0.x + v0.y) + (v0.z + v0.w)) + ((v1.x + v1.y) + (v1.z + v1.w));

    // reduce across the 8 lanes holding this field
    s += __shfl_xor_sync(0xffffffffu, s, 1);
    s += __shfl_xor_sync(0xffffffffu, s, 2);
    s += __shfl_xor_sync(0xffffffffu, s, 4);

    __shared__ float fs[32];
    if ((t & 7) == 0) fs[t >> 3] = s;   // field index = t/8
    __syncthreads();

    if (t < 124) {
        float4 o4;
        float* ov = &o4.x;
        #pragma unroll
        for (int i = 0; i < 4; i++) {
            const int p = 4 * t + i;
            // row index: largest r with T(r) = r*(63-r)/2 <= p
            const float q = __fsqrt_rn((float)(3969 - 8 * p));
            int r = (int)((63.0f - q) * 0.5f);
            // integer fixup against fp rounding at row boundaries
            if (((r + 1) * (62 - r)) >> 1 <= p) r++;
            int Tr = (r * (63 - r)) >> 1;
            if (Tr > p) { r--; Tr = (r * (63 - r)) >> 1; }
            const int c = r + 1 + (p - Tr);
            ov[i] = fs[r] * fs[c];
        }
        reinterpret_cast<float4*>(out + (size_t)b * 496)[t] = o4;
    }
}

extern "C" void kernel_launch(void* const* d_in, const int* in_sizes, int n_in,
                              void* d_out, int out_size) {
    const float4* x = (const float4*)d_in[0];
    float* out = (float*)d_out;
    opn_kernel<<<BATCH, 256>>>(x, out);
}

// round 4
// speedup vs baseline: 1.1824x; 1.1156x over previous
#include <cuda_runtime.h>

// x: [B=16384, F=32, E=64] fp32 contiguous. out: [B, P=496] fp32.
// s[b,f] = sum_e x[b,f,e];  out[b,p] = s[b,row(p)] * s[b,col(p)]
//
// 2 batch rows per CTA (256 threads), grid = 8192.
// Load phase (per row): thread t loads float4 row[t], row[t+256] (fully
//   coalesced). float4 index i belongs to field i>>4, so warp w's first load
//   holds field 2w in lanes 0-15 and field 2w+1 in lanes 16-31; butterfly
//   shfl_xor (8,4,2,1) reduces each 16-lane half.
// Epilogue: static pair table (compile-time constexpr, packed byte offsets
//   r*4 | c*4<<8) -> 1 LDG.64 per thread for 4 pairs, byte-extract, LDS, FMUL,
//   one STG.128 per row. Decode amortized across both rows.

static constexpr int BATCH = 16384;

struct alignas(16) Tbl { unsigned int v[248]; };  // 496 u16 entries, 2 per uint
constexpr Tbl make_tbl() {
    Tbl t{};
    unsigned short tmp[496] = {};
    int k = 0;
    for (int i = 0; i < 31; ++i)
        for (int j = i + 1; j < 32; ++j)
            tmp[k++] = (unsigned short)((i * 4) | ((j * 4) << 8));
    for (int m = 0; m < 248; ++m)
        t.v[m] = (unsigned int)tmp[2 * m] | ((unsigned int)tmp[2 * m + 1] << 16);
    return t;
}
__device__ constexpr Tbl TABLE = make_tbl();

__device__ __forceinline__ float hsum4(float4 v) {
    return (v.x + v.y) + (v.z + v.w);
}

__global__ __launch_bounds__(256) void opn_kernel(const float4* __restrict__ x,
                                                  float* __restrict__ out) {
    const int b0 = blockIdx.x * 2;
    const float4* rowA = x + (size_t)b0 * 512;   // 512 float4 per batch row
    const int t = threadIdx.x;

    float sA0 = hsum4(rowA[t]);
    float sA1 = hsum4(rowA[t + 256]);
    float sB0 = hsum4(rowA[t + 512]);
    float sB1 = hsum4(rowA[t + 768]);

    // reduce within each 16-lane half (fields are 16 consecutive float4)
    #pragma unroll
    for (int o = 8; o >= 1; o >>= 1) {
        sA0 += __shfl_xor_sync(0xffffffffu, sA0, o);
        sA1 += __shfl_xor_sync(0xffffffffu, sA1, o);
        sB0 += __shfl_xor_sync(0xffffffffu, sB0, o);
        sB1 += __shfl_xor_sync(0xffffffffu, sB1, o);
    }

    __shared__ float fsA[32], fsB[32];
    const int lane = t & 31;
    const int w = t >> 5;
    if (lane == 0) {
        fsA[2 * w] = sA0;  fsA[16 + 2 * w] = sA1;
        fsB[2 * w] = sB0;  fsB[16 + 2 * w] = sB1;
    }
    if (lane == 16) {
        fsA[2 * w + 1] = sA0;  fsA[17 + 2 * w] = sA1;
        fsB[2 * w + 1] = sB0;  fsB[17 + 2 * w] = sB1;
    }
    __syncthreads();

    if (t < 124) {
        const uint2 pk = reinterpret_cast<const uint2*>(TABLE.v)[t];  // 4 pairs
        const unsigned r0 =  pk.x        & 0xFFu;
        const unsigned c0 = (pk.x >> 8)  & 0xFFu;
        const unsigned r1 = (pk.x >> 16) & 0xFFu;
        const unsigned c1 =  pk.x >> 24;
        const unsigned r2 =  pk.y        & 0xFFu;
        const unsigned c2 = (pk.y >> 8)  & 0xFFu;
        const unsigned r3 = (pk.y >> 16) & 0xFFu;
        const unsigned c3 =  pk.y >> 24;

        const char* fA = (const char*)fsA;
        const char* fB = (const char*)fsB;

        float4 oA, oB;
        oA.x = *(const float*)(fA + r0) * *(const float*)(fA + c0);
        oA.y = *(const float*)(fA + r1) * *(const float*)(fA + c1);
        oA.z = *(const float*)(fA + r2) * *(const float*)(fA + c2);
        oA.w = *(const float*)(fA + r3) * *(const float*)(fA + c3);
        oB.x = *(const float*)(fB + r0) * *(const float*)(fB + c0);
        oB.y = *(const float*)(fB + r1) * *(const float*)(fB + c1);
        oB.z = *(const float*)(fB + r2) * *(const float*)(fB + c2);
        oB.w = *(const float*)(fB + r3) * *(const float*)(fB + c3);

        reinterpret_cast<float4*>(out + (size_t)b0 * 496)[t]       = oA;
        reinterpret_cast<float4*>(out + (size_t)(b0 + 1) * 496)[t] = oB;
    }
}

extern "C" void kernel_launch(void* const* d_in, const int* in_sizes, int n_in,
                              void* d_out, int out_size) {
    const float4* x = (const float4*)d_in[0];
    float* out = (float*)d_out;
    opn_kernel<<<BATCH / 2, 256>>>(x, out);
}

// round 5
// speedup vs baseline: 1.3589x; 1.1493x over previous
#include <cuda_runtime.h>

// x: [B=16384, F=32, E=64] fp32 contiguous. out: [B, P=496] fp32.
// s[b,f] = sum_e x[b,f,e];  out[b,p] = s[b,row(p)] * s[b,col(p)]
//
// 4 batch rows per CTA (256 threads), grid = 4096.
// Loads: thread t loads float4 base[t + 256k], k=0..7 (fully coalesced,
//   4 rows x 512 float4). Value k: row = k>>1, and within the warp the 16
//   float4 of a field occupy one 16-lane half: field = 2w + 16(k&1) + (lane>=16).
// Reduction: merged butterfly — per 4 values: offset-8 on each (4 shfl),
//   SEL-merge into halves, offset-4 (2 shfl), SEL-merge into quarters,
//   shared offsets 2,1 (2 shfl) = 8 shuffles / 4 values (2 per value,
//   vs 4 for plain butterfly) -> halves shuffle L1/MIO wavefronts.
// Epilogue: static packed byte-offset pair table, smem gather, STG.128.

static constexpr int BATCH = 16384;

struct alignas(16) Tbl { unsigned int v[248]; };  // 496 u16 entries, 2 per uint
constexpr Tbl make_tbl() {
    Tbl t{};
    unsigned short tmp[496] = {};
    int k = 0;
    for (int i = 0; i < 31; ++i)
        for (int j = i + 1; j < 32; ++j)
            tmp[k++] = (unsigned short)((i * 4) | ((j * 4) << 8));
    for (int m = 0; m < 248; ++m)
        t.v[m] = (unsigned int)tmp[2 * m] | ((unsigned int)tmp[2 * m + 1] << 16);
    return t;
}
__device__ constexpr Tbl TABLE = make_tbl();

__device__ __forceinline__ float hsum4(float4 v) {
    return (v.x + v.y) + (v.z + v.w);
}

__global__ __launch_bounds__(256) void opn_kernel(const float4* __restrict__ x,
                                                  float* __restrict__ out) {
    const int b0 = blockIdx.x << 2;
    const float4* base = x + (size_t)b0 * 512;   // 4 rows x 512 float4
    const int t = threadIdx.x;
    const int lane = t & 31;
    const int w = t >> 5;
    const int h = lane >> 4;          // which 16-lane half

    __shared__ float fs[4][32];

    float4 v[8];
    #pragma unroll
    for (int k = 0; k < 8; k++) v[k] = base[t + 256 * k];

    float s[8];
    #pragma unroll
    for (int k = 0; k < 8; k++) s[k] = hsum4(v[k]);

    const unsigned FULL = 0xffffffffu;
    #pragma unroll
    for (int g = 0; g < 2; g++) {
        float A = s[4 * g + 0], B = s[4 * g + 1];
        float C = s[4 * g + 2], D = s[4 * g + 3];
        // step 8 (within each 16-lane half)
        A += __shfl_xor_sync(FULL, A, 8);
        B += __shfl_xor_sync(FULL, B, 8);
        C += __shfl_xor_sync(FULL, C, 8);
        D += __shfl_xor_sync(FULL, D, 8);
        // merge pairs into 8-lane halves
        float M = (lane & 8) ? B : A;
        float N = (lane & 8) ? D : C;
        // step 4
        M += __shfl_xor_sync(FULL, M, 4);
        N += __shfl_xor_sync(FULL, N, 4);
        // merge into 4-lane quarters: groups hold {A, C, B, D}
        float P = (lane & 4) ? N : M;
        // shared steps 2, 1
        P += __shfl_xor_sync(FULL, P, 2);
        P += __shfl_xor_sync(FULL, P, 1);
        // 4-lane group grp holds total of value k = ((grp&1)<<1)|(grp>>1)
        if ((lane & 3) == 0) {
            const int grp = (lane >> 2) & 3;
            const int k = ((grp & 1) << 1) | (grp >> 1);   // {0,2,1,3}
            const int row = 2 * g + (k >> 1);
            const int f = 2 * w + ((k & 1) << 4) + h;
            fs[row][f] = P;
        }
    }
    __syncthreads();

    #pragma unroll
    for (int i = t; i < 496; i += 256) {           // 124 float4-stores x 4 rows
        const int row = i / 124;
        const int idx = i - row * 124;
        const uint2 pk = reinterpret_cast<const uint2*>(TABLE.v)[idx];
        const char* f = (const char*)fs[row];
        float4 o;
        o.x = *(const float*)(f + ( pk.x        & 0xFFu)) * *(const float*)(f + ((pk.x >>  8) & 0xFFu));
        o.y = *(const float*)(f + ((pk.x >> 16) & 0xFFu)) * *(const float*)(f + ( pk.x >> 24        ));
        o.z = *(const float*)(f + ( pk.y        & 0xFFu)) * *(const float*)(f + ((pk.y >>  8) & 0xFFu));
        o.w = *(const float*)(f + ((pk.y >> 16) & 0xFFu)) * *(const float*)(f + ( pk.y >> 24        ));
        reinterpret_cast<float4*>(out + (size_t)(b0 + row) * 496)[idx] = o;
    }
}

extern "C" void kernel_launch(void* const* d_in, const int* in_sizes, int n_in,
                              void* d_out, int out_size) {
    const float4* x = (const float4*)d_in[0];
    float* out = (float*)d_out;
    opn_kernel<<<BATCH / 4, 256>>>(x, out);
}